// round 1
// baseline (speedup 1.0000x reference)
#include <cuda_runtime.h>
#include <cuda_bf16.h>
#include <math.h>

// Problem constants (fixed shapes from reference)
#define B_ 2
#define N_ 12288
#define D_ 256
#define TI 64
#define TJ 64
#define TK 16
#define NSPLIT 4
#define CONF_THRESH 0.8f

// ---------------- device scratch (no allocations allowed) ----------------
__device__ float        g_V[(size_t)B_ * N_ * D_];   // compacted normalized valid columns
__device__ float        g_R[(size_t)B_ * N_ * D_];   // compacted normalized invalid rows
__device__ int          g_nval[B_];
__device__ int          g_ninv[B_];
__device__ unsigned int g_rmax[B_ * N_];             // monotonic-encoded per-row max
__device__ double       g_contrib[B_];
__device__ int          g_nconf[B_];
__device__ int          g_mask_mode;                 // 0=int32, 1=uint8, 2=float32

// ---------------- init ----------------
__global__ void init_kernel() {
    int i = blockIdx.x * blockDim.x + threadIdx.x;
    if (i < B_ * N_) g_rmax[i] = 0u;
    if (i < B_) {
        g_nval[i] = 0;
        g_ninv[i] = 0;
        g_nconf[i] = 0;
        g_contrib[i] = 0.0;
    }
}

// ---------------- mask dtype detection ----------------
// Reads only the first B_*N_ bytes (safe for any of the 3 candidate dtypes).
// f32 bool (0.0/1.0): byte%4==3 is 0x3f when true.
// uint8 bool: nonzero bytes at positions %4 != 0.
// int32 bool: nonzero only at positions %4 == 0.
__global__ void detect_kernel(const unsigned char* __restrict__ mraw) {
    __shared__ int s_f3f, s_foff;
    if (threadIdx.x == 0) { s_f3f = 0; s_foff = 0; }
    __syncthreads();
    int f3f = 0, foff = 0;
    for (int i = threadIdx.x; i < B_ * N_; i += blockDim.x) {
        unsigned char c = mraw[i];
        if ((i & 3) == 3 && c == 0x3f) f3f = 1;
        if ((i & 3) != 0 && c != 0)    foff = 1;
    }
    if (f3f)  atomicOr(&s_f3f, 1);
    if (foff) atomicOr(&s_foff, 1);
    __syncthreads();
    if (threadIdx.x == 0)
        g_mask_mode = s_f3f ? 2 : (s_foff ? 1 : 0);
}

// ---------------- normalize + compact (one warp per point) ----------------
__global__ void norm_compact_kernel(const float* __restrict__ feat,
                                    const void*  __restrict__ mraw) {
    int gw   = (int)((blockIdx.x * blockDim.x + threadIdx.x) >> 5);
    int lane = threadIdx.x & 31;
    if (gw >= B_ * N_) return;
    int b = gw / N_;

    int mv = 0;
    if (lane == 0) {
        int mode = g_mask_mode;
        if (mode == 0)      mv = (((const int*)mraw)[gw] != 0);
        else if (mode == 1) mv = (((const unsigned char*)mraw)[gw] != 0);
        else                mv = (((const float*)mraw)[gw] != 0.0f);
    }
    mv = __shfl_sync(0xffffffffu, mv, 0);

    const float* src = feat + (size_t)gw * D_;
    float4 v0 = ((const float4*)src)[lane];
    float4 v1 = ((const float4*)src)[lane + 32];
    float ss = v0.x * v0.x + v0.y * v0.y + v0.z * v0.z + v0.w * v0.w
             + v1.x * v1.x + v1.y * v1.y + v1.z * v1.z + v1.w * v1.w;
#pragma unroll
    for (int o = 16; o; o >>= 1) ss += __shfl_xor_sync(0xffffffffu, ss, o);
    float inv = 1.0f / fmaxf(sqrtf(ss), 1e-12f);
    v0.x *= inv; v0.y *= inv; v0.z *= inv; v0.w *= inv;
    v1.x *= inv; v1.y *= inv; v1.z *= inv; v1.w *= inv;

    int slot = 0;
    if (lane == 0)
        slot = atomicAdd(mv ? &g_nval[b] : &g_ninv[b], 1);
    slot = __shfl_sync(0xffffffffu, slot, 0);

    float* dst = (mv ? g_V : g_R) + ((size_t)b * N_ + slot) * D_;
    ((float4*)dst)[lane]      = v0;
    ((float4*)dst)[lane + 32] = v1;
}

// ---------------- tiled max-dot kernel ----------------
// grid: (ceil(N/TI), B, NSPLIT), block 256 = 16x16 threads, 4x4 per thread.
__global__ __launch_bounds__(256) void maxsim_kernel() {
    int b = blockIdx.y;
    int ni = g_ninv[b];
    int nv = g_nval[b];
    int row0 = blockIdx.x * TI;
    if (row0 >= ni || nv == 0) return;

    int chunk = (((nv + NSPLIT - 1) / NSPLIT) + TJ - 1) / TJ * TJ;
    int jbeg = blockIdx.z * chunk;
    int jend = min(nv, jbeg + chunk);
    if (jbeg >= jend) return;

    const float* Rb = g_R + (size_t)b * N_ * D_;
    const float* Vb = g_V + (size_t)b * N_ * D_;

    __shared__ float As[TK][TI + 1];
    __shared__ float Bs[TK][TJ + 1];
    __shared__ float smax[TI][17];

    int tid = threadIdx.x;
    int tx = tid & 15, ty = tid >> 4;
    int lrow = tid >> 2;
    int lk   = (tid & 3) * 4;

    float rmax[4] = {-3.4e38f, -3.4e38f, -3.4e38f, -3.4e38f};
    int  ar  = row0 + lrow;
    bool aok = (ar < ni);

    for (int j0 = jbeg; j0 < jend; j0 += TJ) {
        float acc[4][4] = {{0.f,0.f,0.f,0.f},{0.f,0.f,0.f,0.f},
                           {0.f,0.f,0.f,0.f},{0.f,0.f,0.f,0.f}};
        int  br  = j0 + lrow;
        bool bok = (br < jend);

        for (int k0 = 0; k0 < D_; k0 += TK) {
            float4 av = make_float4(0.f, 0.f, 0.f, 0.f);
            float4 bv = make_float4(0.f, 0.f, 0.f, 0.f);
            if (aok) av = *(const float4*)(Rb + (size_t)ar * D_ + k0 + lk);
            if (bok) bv = *(const float4*)(Vb + (size_t)br * D_ + k0 + lk);
            __syncthreads();
            As[lk + 0][lrow] = av.x; As[lk + 1][lrow] = av.y;
            As[lk + 2][lrow] = av.z; As[lk + 3][lrow] = av.w;
            Bs[lk + 0][lrow] = bv.x; Bs[lk + 1][lrow] = bv.y;
            Bs[lk + 2][lrow] = bv.z; Bs[lk + 3][lrow] = bv.w;
            __syncthreads();
#pragma unroll
            for (int k = 0; k < TK; ++k) {
                float a[4], bb[4];
#pragma unroll
                for (int r = 0; r < 4; ++r) a[r]  = As[k][ty * 4 + r];
#pragma unroll
                for (int c = 0; c < 4; ++c) bb[c] = Bs[k][tx * 4 + c];
#pragma unroll
                for (int r = 0; r < 4; ++r)
#pragma unroll
                    for (int c = 0; c < 4; ++c)
                        acc[r][c] = fmaf(a[r], bb[c], acc[r][c]);
            }
        }
#pragma unroll
        for (int r = 0; r < 4; ++r)
            rmax[r] = fmaxf(rmax[r],
                       fmaxf(fmaxf(acc[r][0], acc[r][1]),
                             fmaxf(acc[r][2], acc[r][3])));
    }

    __syncthreads();
#pragma unroll
    for (int r = 0; r < 4; ++r) smax[ty * 4 + r][tx] = rmax[r];
    __syncthreads();

    if (tid < TI) {
        float m = smax[tid][0];
#pragma unroll
        for (int x = 1; x < 16; ++x) m = fmaxf(m, smax[tid][x]);
        int grow = row0 + tid;
        if (grow < ni) {
            int rep = __float_as_int(m);
            unsigned key = (rep < 0) ? ~((unsigned)rep)
                                     : ((unsigned)rep | 0x80000000u);
            atomicMax(&g_rmax[b * N_ + grow], key);
        }
    }
}

// ---------------- confidence / contribution pass ----------------
__global__ void confident_kernel() {
    int i = blockIdx.x * blockDim.x + threadIdx.x;
    if (i >= B_ * N_) return;
    int b = i / N_;
    int row = i - b * N_;
    if (row >= g_ninv[b]) return;
    unsigned key = g_rmax[i];
    float m;
    if (key & 0x80000000u) m = __uint_as_float(key & 0x7fffffffu);
    else                   m = __uint_as_float(~key);
    if (m > CONF_THRESH) {
        atomicAdd(&g_contrib[b], (double)(1.0f - m));
        atomicAdd(&g_nconf[b], 1);
    }
}

// ---------------- finalize ----------------
__global__ void finalize_kernel(float* out) {
    if (threadIdx.x == 0 && blockIdx.x == 0) {
        double tl = 0.0, tp = 0.0;
        for (int b = 0; b < B_; ++b) {
            int ni = g_ninv[b], nvv = g_nval[b], nc = g_nconf[b];
            bool active = (nc > 0) && (nvv > 0) && (ni > 0);
            if (active) {
                double pseudo = g_contrib[b] / (double)(nc > 1 ? nc : 1);
                tl += pseudo * (double)ni;
                tp += (double)ni;
            }
        }
        out[0] = (tp > 0.0) ? (float)(0.01 * tl / tp) : 0.0f;
    }
}

// ---------------- launch ----------------
extern "C" void kernel_launch(void* const* d_in, const int* in_sizes, int n_in,
                              void* d_out, int out_size) {
    // feat_3d is the big input; be robust to ordering.
    int fi = 0, mi = 1;
    if (n_in >= 2 && in_sizes[0] < in_sizes[1]) { fi = 1; mi = 0; }
    const float* feat = (const float*)d_in[fi];
    const void*  mask = d_in[mi];

    init_kernel<<<(B_ * N_ + 255) / 256, 256>>>();
    detect_kernel<<<1, 1024>>>((const unsigned char*)mask);
    norm_compact_kernel<<<(B_ * N_ * 32 + 255) / 256, 256>>>(feat, mask);
    dim3 g((N_ + TI - 1) / TI, B_, NSPLIT);
    maxsim_kernel<<<g, 256>>>();
    confident_kernel<<<(B_ * N_ + 255) / 256, 256>>>();
    finalize_kernel<<<1, 32>>>((float*)d_out);
}

// round 4
// speedup vs baseline: 2.8256x; 2.8256x over previous
#include <cuda_runtime.h>
#include <cuda_bf16.h>
#include <math.h>
#include <stdint.h>

// Problem constants
#define B_ 2
#define N_ 12288
#define D_ 256
#define CONF_THRESH 0.8f

// ---------------- device scratch (no allocations allowed) ----------------
__device__ __nv_bfloat16 g_Vhi[(size_t)B_ * N_ * D_];
__device__ __nv_bfloat16 g_Vlo[(size_t)B_ * N_ * D_];
__device__ __nv_bfloat16 g_Rhi[(size_t)B_ * N_ * D_];
__device__ __nv_bfloat16 g_Rlo[(size_t)B_ * N_ * D_];
__device__ int    g_nval[B_];
__device__ int    g_ninv[B_];
__device__ int    g_nconf[B_];
__device__ float  g_rmaxf[B_ * N_];
__device__ double g_contrib[B_];
__device__ int    g_mask_mode;   // 0=int32, 1=uint8, 2=float32

// SMEM layout (bytes):
//   A tile  : [0, 131072)      = 2 parts x 128 rows x 256 k bf16 (32 u16B/row), SW128 atoms
//   B bufs  : [131072, 196608) = 2 buffers x (2 parts x 128 cols x 64 k bf16)
//   rowmax  : [196608, 197632) = 2 x 128 floats
#define SM_A    0u
#define SM_B    131072u
#define SM_MAX  196608u
#define SMEM_BYTES 197632

// ---------------- small helpers ----------------
__device__ __forceinline__ uint32_t smem_u32_addr(const void* p) {
    uint32_t a;
    asm("{ .reg .u64 t; cvta.to.shared.u64 t, %1; cvt.u32.u64 %0, t; }"
        : "=r"(a) : "l"(p));
    return a;
}
__device__ __forceinline__ uint32_t sw128(uint32_t off) {
    return off ^ ((off >> 3) & 0x70u);
}
__device__ __forceinline__ void ldmatrix_x4(uint32_t* r, uint32_t addr) {
    asm volatile("ldmatrix.sync.aligned.m8n8.x4.shared.b16 {%0,%1,%2,%3}, [%4];"
                 : "=r"(r[0]), "=r"(r[1]), "=r"(r[2]), "=r"(r[3]) : "r"(addr));
}
__device__ __forceinline__ void mma16816(float* c, const uint32_t* a,
                                         uint32_t b0, uint32_t b1) {
    asm volatile(
        "mma.sync.aligned.m16n8k16.row.col.f32.bf16.bf16.f32 "
        "{%0,%1,%2,%3}, {%4,%5,%6,%7}, {%8,%9}, {%0,%1,%2,%3};"
        : "+f"(c[0]), "+f"(c[1]), "+f"(c[2]), "+f"(c[3])
        : "r"(a[0]), "r"(a[1]), "r"(a[2]), "r"(a[3]), "r"(b0), "r"(b1));
}
__device__ __forceinline__ void cp_async16(uint32_t saddr, const void* gaddr, int sz) {
    asm volatile("cp.async.ca.shared.global [%0], [%1], 16, %2;"
                 :: "r"(saddr), "l"(gaddr), "r"(sz));
}
__device__ __forceinline__ void cp_commit() {
    asm volatile("cp.async.commit_group;");
}
template <int N>
__device__ __forceinline__ void cp_wait() {
    asm volatile("cp.async.wait_group %0;" :: "n"(N));
}

// ---------------- init ----------------
__global__ void init_kernel() {
    int i = threadIdx.x;
    if (i < B_) {
        g_nval[i] = 0; g_ninv[i] = 0; g_nconf[i] = 0; g_contrib[i] = 0.0;
    }
}

// ---------------- mask dtype detection ----------------
__global__ void detect_kernel(const unsigned char* __restrict__ mraw) {
    __shared__ int s_f3f, s_foff;
    if (threadIdx.x == 0) { s_f3f = 0; s_foff = 0; }
    __syncthreads();
    int f3f = 0, foff = 0;
    for (int i = threadIdx.x; i < B_ * N_; i += blockDim.x) {
        unsigned char c = mraw[i];
        if ((i & 3) == 3 && c == 0x3f) f3f = 1;
        if ((i & 3) != 0 && c != 0)    foff = 1;
    }
    if (f3f)  atomicOr(&s_f3f, 1);
    if (foff) atomicOr(&s_foff, 1);
    __syncthreads();
    if (threadIdx.x == 0) g_mask_mode = s_f3f ? 2 : (s_foff ? 1 : 0);
}

// ---------------- normalize + split + compact (one warp per point) ----------------
__device__ __forceinline__ void split_pack(float4 v, uint2& hi, uint2& lo) {
    __nv_bfloat16 hx = __float2bfloat16(v.x), hy = __float2bfloat16(v.y);
    __nv_bfloat16 hz = __float2bfloat16(v.z), hw = __float2bfloat16(v.w);
    float lx = v.x - __bfloat162float(hx), ly = v.y - __bfloat162float(hy);
    float lz = v.z - __bfloat162float(hz), lw = v.w - __bfloat162float(hw);
    __nv_bfloat162 h0 = __halves2bfloat162(hx, hy);
    __nv_bfloat162 h1 = __halves2bfloat162(hz, hw);
    __nv_bfloat162 l0 = __floats2bfloat162_rn(lx, ly);
    __nv_bfloat162 l1 = __floats2bfloat162_rn(lz, lw);
    hi.x = *(uint32_t*)&h0; hi.y = *(uint32_t*)&h1;
    lo.x = *(uint32_t*)&l0; lo.y = *(uint32_t*)&l1;
}

__global__ void norm_compact_kernel(const float* __restrict__ feat,
                                    const void*  __restrict__ mraw) {
    int gw   = (int)((blockIdx.x * blockDim.x + threadIdx.x) >> 5);
    int lane = threadIdx.x & 31;
    if (gw >= B_ * N_) return;
    int b = gw / N_;

    int mv = 0;
    if (lane == 0) {
        int mode = g_mask_mode;
        if (mode == 0)      mv = (((const int*)mraw)[gw] != 0);
        else if (mode == 1) mv = (((const unsigned char*)mraw)[gw] != 0);
        else                mv = (((const float*)mraw)[gw] != 0.0f);
    }
    mv = __shfl_sync(0xffffffffu, mv, 0);

    const float* src = feat + (size_t)gw * D_;
    float4 v0 = ((const float4*)src)[lane];
    float4 v1 = ((const float4*)src)[lane + 32];
    float ss = v0.x * v0.x + v0.y * v0.y + v0.z * v0.z + v0.w * v0.w
             + v1.x * v1.x + v1.y * v1.y + v1.z * v1.z + v1.w * v1.w;
#pragma unroll
    for (int o = 16; o; o >>= 1) ss += __shfl_xor_sync(0xffffffffu, ss, o);
    float inv = 1.0f / fmaxf(sqrtf(ss), 1e-12f);
    v0.x *= inv; v0.y *= inv; v0.z *= inv; v0.w *= inv;
    v1.x *= inv; v1.y *= inv; v1.z *= inv; v1.w *= inv;

    int slot = 0;
    if (lane == 0)
        slot = atomicAdd(mv ? &g_nval[b] : &g_ninv[b], 1);
    slot = __shfl_sync(0xffffffffu, slot, 0);

    size_t base = ((size_t)b * N_ + slot) * D_;
    __nv_bfloat16* dh = (mv ? g_Vhi : g_Rhi) + base;
    __nv_bfloat16* dl = (mv ? g_Vlo : g_Rlo) + base;
    uint2 h, l;
    split_pack(v0, h, l);
    ((uint2*)dh)[lane] = h;      ((uint2*)dl)[lane] = l;
    split_pack(v1, h, l);
    ((uint2*)dh)[32 + lane] = h; ((uint2*)dl)[32 + lane] = l;
}

// ---------------- main HMMA max-sim kernel ----------------
// grid (N_/128, B_), 256 threads (8 warps: 4 m-warps x 2 n-warps).
// A (R-rows tile, hi+lo) resident in SMEM; B (V cols) streamed in k64 chunks.
__global__ __launch_bounds__(256, 1) void maxsim_hmma() {
    extern __shared__ __align__(1024) char smem[];
    int b = blockIdx.y;
    int ni = g_ninv[b], nv = g_nval[b];
    int row0 = blockIdx.x * 128;
    if (row0 >= ni || nv <= 0) return;

    uint32_t sb = smem_u32_addr(smem);
    int tid = threadIdx.x;
    int lane = tid & 31, warp = tid >> 5;
    int warp_m = warp & 3, warp_n = warp >> 2;

    const __nv_bfloat16* Rhi_b = g_Rhi + (size_t)b * N_ * D_;
    const __nv_bfloat16* Rlo_b = g_Rlo + (size_t)b * N_ * D_;
    const __nv_bfloat16* Vhi_b = g_Vhi + (size_t)b * N_ * D_;
    const __nv_bfloat16* Vlo_b = g_Vlo + (size_t)b * N_ * D_;

    // ---- load resident A tile: 2 parts x 128 rows x 32 u16B-units per row
    //      (D=256 bf16 = 512 bytes = 32 uint4 units) => 8192 uint4 total
#pragma unroll
    for (int it = 0; it < 32; ++it) {
        int u = tid + it * 256;            // 0..8191
        int part = u >> 12;                // 0..1
        int rem  = u & 4095;
        int row  = rem >> 5;               // 0..127
        int ku   = rem & 31;               // 0..31
        int gr   = min(row0 + row, ni - 1);
        const uint4* src = (const uint4*)((part ? Rlo_b : Rhi_b) + (size_t)gr * D_) + ku;
        uint32_t off = SM_A + (uint32_t)part * 65536u
                     + (uint32_t)((row >> 3) * 4 + (ku >> 3)) * 1024u
                     + (uint32_t)(row & 7) * 128u + (uint32_t)(ku & 7) * 16u;
        *(uint4*)(smem + sw128(off)) = *src;
    }

    float acc[2][8][4];
#pragma unroll
    for (int mf = 0; mf < 2; ++mf)
#pragma unroll
        for (int nf = 0; nf < 8; ++nf)
#pragma unroll
            for (int q = 0; q < 4; ++q) acc[mf][nf][q] = 0.0f;
    float rm[4] = {-INFINITY, -INFINITY, -INFINITY, -INFINITY};

    int T = (nv + 127) >> 7;
    int NC = T * 4;

    // chunk copier: chunk c covers j-tile (c>>2), k range (c&3)*64, both parts
    auto cp_chunk = [&](int c, int bufsel) {
        int jt = c >> 2, kc = c & 3;
        int col0 = jt * 128;
#pragma unroll
        for (int i = 0; i < 8; ++i) {
            int u = tid + i * 256;          // 0..2047
            int part = u >> 10;
            int rem  = u & 1023;
            int col  = rem >> 3;
            int ku   = rem & 7;
            int gc   = col0 + col;
            const void* src = (const void*)((part ? Vlo_b : Vhi_b)
                              + (size_t)gc * D_ + kc * 64 + ku * 8);
            uint32_t off = SM_B + (uint32_t)bufsel * 32768u + (uint32_t)part * 16384u
                         + (uint32_t)(col >> 3) * 1024u
                         + (uint32_t)(col & 7) * 128u + (uint32_t)ku * 16u;
            cp_async16(sb + sw128(off), src, (gc < nv) ? 16 : 0);
        }
        cp_commit();
    };

    cp_chunk(0, 0);
    __syncthreads();   // A tile visible to all

    for (int i = 0; i < NC; ++i) {
        int bufsel = i & 1;
        int kc = i & 3;
        if (i + 1 < NC) { cp_chunk(i + 1, (i + 1) & 1); cp_wait<1>(); }
        else            { cp_wait<0>(); }
        __syncthreads();

        // ---- compute chunk: 3 combos x 4 k16 steps
#pragma unroll
        for (int combo = 0; combo < 3; ++combo) {
            uint32_t apart = (combo == 2) ? 65536u : 0u;
            uint32_t bpart = (combo == 1) ? 16384u : 0u;
#pragma unroll
            for (int kk = 0; kk < 4; ++kk) {
                uint32_t a[2][4];
#pragma unroll
                for (int mf = 0; mf < 2; ++mf) {
                    int row = warp_m * 32 + mf * 16 + (lane & 15);
                    int ku  = (kc * 4 + kk) * 2 + (lane >> 4);
                    uint32_t off = SM_A + apart
                                 + (uint32_t)((row >> 3) * 4 + (ku >> 3)) * 1024u
                                 + (uint32_t)(row & 7) * 128u
                                 + (uint32_t)(ku & 7) * 16u;
                    ldmatrix_x4(a[mf], sb + sw128(off));
                }
                uint32_t bf[4][4];
#pragma unroll
                for (int nf2 = 0; nf2 < 4; ++nf2) {
                    int col = warp_n * 64 + nf2 * 16 + (lane & 15);
                    int ku  = kk * 2 + (lane >> 4);
                    uint32_t off = SM_B + (uint32_t)bufsel * 32768u + bpart
                                 + (uint32_t)(col >> 3) * 1024u
                                 + (uint32_t)(col & 7) * 128u
                                 + (uint32_t)ku * 16u;
                    ldmatrix_x4(bf[nf2], sb + sw128(off));
                }
#pragma unroll
                for (int mf = 0; mf < 2; ++mf)
#pragma unroll
                    for (int nf2 = 0; nf2 < 4; ++nf2) {
                        mma16816(acc[mf][nf2 * 2],     a[mf], bf[nf2][0], bf[nf2][2]);
                        mma16816(acc[mf][nf2 * 2 + 1], a[mf], bf[nf2][1], bf[nf2][3]);
                    }
            }
        }

        if (kc == 3) {
            // end of j-tile: fold accumulators into running row-max, reset
#pragma unroll
            for (int mf = 0; mf < 2; ++mf) {
                float m0 = rm[mf * 2], m1 = rm[mf * 2 + 1];
#pragma unroll
                for (int nf = 0; nf < 8; ++nf) {
                    m0 = fmaxf(m0, fmaxf(acc[mf][nf][0], acc[mf][nf][1]));
                    m1 = fmaxf(m1, fmaxf(acc[mf][nf][2], acc[mf][nf][3]));
#pragma unroll
                    for (int q = 0; q < 4; ++q) acc[mf][nf][q] = 0.0f;
                }
                rm[mf * 2] = m0; rm[mf * 2 + 1] = m1;
            }
        }
        __syncthreads();
    }

    // ---- reduce row maxima: lanes sharing a row are lane%4 groups
#pragma unroll
    for (int j = 0; j < 4; ++j) {
        rm[j] = fmaxf(rm[j], __shfl_xor_sync(0xffffffffu, rm[j], 1));
        rm[j] = fmaxf(rm[j], __shfl_xor_sync(0xffffffffu, rm[j], 2));
    }
    float* smax = (float*)(smem + SM_MAX);
    if ((lane & 3) == 0) {
        int rbase = warp_m * 32 + (lane >> 2);
#pragma unroll
        for (int mf = 0; mf < 2; ++mf) {
            smax[warp_n * 128 + rbase + mf * 16]     = rm[mf * 2];
            smax[warp_n * 128 + rbase + mf * 16 + 8] = rm[mf * 2 + 1];
        }
    }
    __syncthreads();
    if (tid < 128) {
        int row = row0 + tid;
        if (row < ni)
            g_rmaxf[b * N_ + row] = fmaxf(smax[tid], smax[128 + tid]);
    }
}

// ---------------- confidence / contribution pass ----------------
__global__ void confident_kernel() {
    int i = blockIdx.x * blockDim.x + threadIdx.x;
    if (i >= B_ * N_) return;
    int b = i / N_;
    int row = i - b * N_;
    if (g_nval[b] <= 0) return;
    if (row >= g_ninv[b]) return;
    float m = g_rmaxf[i];
    if (m > CONF_THRESH) {
        atomicAdd(&g_contrib[b], (double)(1.0f - m));
        atomicAdd(&g_nconf[b], 1);
    }
}

// ---------------- finalize ----------------
__global__ void finalize_kernel(float* out) {
    if (threadIdx.x == 0 && blockIdx.x == 0) {
        double tl = 0.0, tp = 0.0;
        for (int b = 0; b < B_; ++b) {
            int ni = g_ninv[b], nvv = g_nval[b], nc = g_nconf[b];
            bool active = (nc > 0) && (nvv > 0) && (ni > 0);
            if (active) {
                double pseudo = g_contrib[b] / (double)(nc > 1 ? nc : 1);
                tl += pseudo * (double)ni;
                tp += (double)ni;
            }
        }
        out[0] = (tp > 0.0) ? (float)(0.01 * tl / tp) : 0.0f;
    }
}

// ---------------- launch ----------------
extern "C" void kernel_launch(void* const* d_in, const int* in_sizes, int n_in,
                              void* d_out, int out_size) {
    int fi = 0, mi = 1;
    if (n_in >= 2 && in_sizes[0] < in_sizes[1]) { fi = 1; mi = 0; }
    const float* feat = (const float*)d_in[fi];
    const void*  mask = d_in[mi];

    cudaFuncSetAttribute(maxsim_hmma, cudaFuncAttributeMaxDynamicSharedMemorySize,
                         SMEM_BYTES);

    init_kernel<<<1, 32>>>();
    detect_kernel<<<1, 1024>>>((const unsigned char*)mask);
    norm_compact_kernel<<<(B_ * N_ * 32 + 255) / 256, 256>>>(feat, mask);
    dim3 g(N_ / 128, B_);
    maxsim_hmma<<<g, 256, SMEM_BYTES>>>();
    confident_kernel<<<(B_ * N_ + 255) / 256, 256>>>();
    finalize_kernel<<<1, 32>>>((float*)d_out);
}

// round 5
// speedup vs baseline: 4.1723x; 1.4766x over previous
#include <cuda_runtime.h>
#include <cuda_bf16.h>
#include <math.h>
#include <stdint.h>

// Problem constants
#define B_ 2
#define N_ 12288
#define D_ 256
#define CONF_THRESH 0.8f
#define JSPLIT 3

// ---------------- device scratch (no allocations allowed) ----------------
__device__ __nv_bfloat16 g_Vhi[(size_t)B_ * N_ * D_];
__device__ __nv_bfloat16 g_Vlo[(size_t)B_ * N_ * D_];
__device__ __nv_bfloat16 g_Rhi[(size_t)B_ * N_ * D_];
__device__ __nv_bfloat16 g_Rlo[(size_t)B_ * N_ * D_];
__device__ int      g_nval[B_];
__device__ int      g_ninv[B_];
__device__ int      g_nconf[B_];
__device__ unsigned g_rmax[B_ * N_];     // monotonic-encoded float max
__device__ double   g_contrib[B_];
__device__ int      g_mask_mode;         // 0=int32, 1=uint8, 2=float32

// SMEM layout (bytes):
//   A tile  : [0, 131072)      = 2 parts x 128 rows x 256 k bf16 (32 u16B/row), SW128 atoms
//   B bufs  : [131072, 196608) = 2 buffers x (2 parts x 128 cols x 64 k bf16)
//   rowmax  : [196608, 197632) = 2 x 128 floats
#define SM_A    0u
#define SM_B    131072u
#define SM_MAX  196608u
#define SMEM_BYTES 197632

// ---------------- small helpers ----------------
__device__ __forceinline__ uint32_t smem_u32_addr(const void* p) {
    uint32_t a;
    asm("{ .reg .u64 t; cvta.to.shared.u64 t, %1; cvt.u32.u64 %0, t; }"
        : "=r"(a) : "l"(p));
    return a;
}
__device__ __forceinline__ uint32_t sw128(uint32_t off) {
    return off ^ ((off >> 3) & 0x70u);
}
__device__ __forceinline__ void ldmatrix_x4(uint32_t* r, uint32_t addr) {
    asm volatile("ldmatrix.sync.aligned.m8n8.x4.shared.b16 {%0,%1,%2,%3}, [%4];"
                 : "=r"(r[0]), "=r"(r[1]), "=r"(r[2]), "=r"(r[3]) : "r"(addr));
}
__device__ __forceinline__ void mma16816(float* c, const uint32_t* a,
                                         uint32_t b0, uint32_t b1) {
    asm volatile(
        "mma.sync.aligned.m16n8k16.row.col.f32.bf16.bf16.f32 "
        "{%0,%1,%2,%3}, {%4,%5,%6,%7}, {%8,%9}, {%0,%1,%2,%3};"
        : "+f"(c[0]), "+f"(c[1]), "+f"(c[2]), "+f"(c[3])
        : "r"(a[0]), "r"(a[1]), "r"(a[2]), "r"(a[3]), "r"(b0), "r"(b1));
}
__device__ __forceinline__ void cp_async16(uint32_t saddr, const void* gaddr, int sz) {
    asm volatile("cp.async.ca.shared.global [%0], [%1], 16, %2;"
                 :: "r"(saddr), "l"(gaddr), "r"(sz));
}
__device__ __forceinline__ void cp_commit() {
    asm volatile("cp.async.commit_group;");
}
template <int N>
__device__ __forceinline__ void cp_wait() {
    asm volatile("cp.async.wait_group %0;" :: "n"(N));
}
__device__ __forceinline__ unsigned enc_max(float m) {
    int rep = __float_as_int(m);
    return (rep < 0) ? ~((unsigned)rep) : ((unsigned)rep | 0x80000000u);
}
__device__ __forceinline__ float dec_max(unsigned key) {
    return (key & 0x80000000u) ? __uint_as_float(key & 0x7fffffffu)
                               : __uint_as_float(~key);
}

// ---------------- init ----------------
__global__ void init_kernel() {
    int i = blockIdx.x * blockDim.x + threadIdx.x;
    if (i < B_ * N_) g_rmax[i] = 0u;
    if (i < B_) {
        g_nval[i] = 0; g_ninv[i] = 0; g_nconf[i] = 0; g_contrib[i] = 0.0;
    }
}

// ---------------- mask dtype detection ----------------
__global__ void detect_kernel(const unsigned char* __restrict__ mraw) {
    __shared__ int s_f3f, s_foff;
    if (threadIdx.x == 0) { s_f3f = 0; s_foff = 0; }
    __syncthreads();
    int f3f = 0, foff = 0;
    for (int i = threadIdx.x; i < B_ * N_; i += blockDim.x) {
        unsigned char c = mraw[i];
        if ((i & 3) == 3 && c == 0x3f) f3f = 1;
        if ((i & 3) != 0 && c != 0)    foff = 1;
    }
    if (f3f)  atomicOr(&s_f3f, 1);
    if (foff) atomicOr(&s_foff, 1);
    __syncthreads();
    if (threadIdx.x == 0) g_mask_mode = s_f3f ? 2 : (s_foff ? 1 : 0);
}

// ---------------- normalize + split + compact (one warp per point) ----------------
__device__ __forceinline__ void split_pack(float4 v, uint2& hi, uint2& lo) {
    __nv_bfloat16 hx = __float2bfloat16(v.x), hy = __float2bfloat16(v.y);
    __nv_bfloat16 hz = __float2bfloat16(v.z), hw = __float2bfloat16(v.w);
    float lx = v.x - __bfloat162float(hx), ly = v.y - __bfloat162float(hy);
    float lz = v.z - __bfloat162float(hz), lw = v.w - __bfloat162float(hw);
    __nv_bfloat162 h0 = __halves2bfloat162(hx, hy);
    __nv_bfloat162 h1 = __halves2bfloat162(hz, hw);
    __nv_bfloat162 l0 = __floats2bfloat162_rn(lx, ly);
    __nv_bfloat162 l1 = __floats2bfloat162_rn(lz, lw);
    hi.x = *(uint32_t*)&h0; hi.y = *(uint32_t*)&h1;
    lo.x = *(uint32_t*)&l0; lo.y = *(uint32_t*)&l1;
}

__global__ void norm_compact_kernel(const float* __restrict__ feat,
                                    const void*  __restrict__ mraw) {
    int gw   = (int)((blockIdx.x * blockDim.x + threadIdx.x) >> 5);
    int lane = threadIdx.x & 31;
    if (gw >= B_ * N_) return;
    int b = gw / N_;

    int mv = 0;
    if (lane == 0) {
        int mode = g_mask_mode;
        if (mode == 0)      mv = (((const int*)mraw)[gw] != 0);
        else if (mode == 1) mv = (((const unsigned char*)mraw)[gw] != 0);
        else                mv = (((const float*)mraw)[gw] != 0.0f);
    }
    mv = __shfl_sync(0xffffffffu, mv, 0);

    const float* src = feat + (size_t)gw * D_;
    float4 v0 = ((const float4*)src)[lane];
    float4 v1 = ((const float4*)src)[lane + 32];
    float ss = v0.x * v0.x + v0.y * v0.y + v0.z * v0.z + v0.w * v0.w
             + v1.x * v1.x + v1.y * v1.y + v1.z * v1.z + v1.w * v1.w;
#pragma unroll
    for (int o = 16; o; o >>= 1) ss += __shfl_xor_sync(0xffffffffu, ss, o);
    float inv = 1.0f / fmaxf(sqrtf(ss), 1e-12f);
    v0.x *= inv; v0.y *= inv; v0.z *= inv; v0.w *= inv;
    v1.x *= inv; v1.y *= inv; v1.z *= inv; v1.w *= inv;

    int slot = 0;
    if (lane == 0)
        slot = atomicAdd(mv ? &g_nval[b] : &g_ninv[b], 1);
    slot = __shfl_sync(0xffffffffu, slot, 0);

    size_t base = ((size_t)b * N_ + slot) * D_;
    __nv_bfloat16* dh = (mv ? g_Vhi : g_Rhi) + base;
    __nv_bfloat16* dl = (mv ? g_Vlo : g_Rlo) + base;
    uint2 h, l;
    split_pack(v0, h, l);
    ((uint2*)dh)[lane] = h;      ((uint2*)dl)[lane] = l;
    split_pack(v1, h, l);
    ((uint2*)dh)[32 + lane] = h; ((uint2*)dl)[32 + lane] = l;
}

// ---------------- main HMMA max-sim kernel ----------------
// grid (N_/128, B_, JSPLIT), 256 threads (8 warps: 4 m-warps x 2 n-warps).
// A (R-rows tile, hi+lo) resident in SMEM; this CTA's V-column slice streamed
// in k64 chunks. Per-row maxima merged globally with atomicMax.
__global__ __launch_bounds__(256, 1) void maxsim_hmma() {
    extern __shared__ __align__(1024) char smem[];
    int b = blockIdx.y;
    int ni = g_ninv[b], nv = g_nval[b];
    int row0 = blockIdx.x * 128;
    if (row0 >= ni || nv <= 0) return;

    // column slice for this split (multiple of 128)
    int tiles_total = (nv + 127) >> 7;
    int tiles_per   = (tiles_total + JSPLIT - 1) / JSPLIT;
    int jbeg = blockIdx.z * tiles_per * 128;
    int jend = min(nv, jbeg + tiles_per * 128);
    if (jbeg >= jend) return;

    uint32_t sb = smem_u32_addr(smem);
    int tid = threadIdx.x;
    int lane = tid & 31, warp = tid >> 5;
    int warp_m = warp & 3, warp_n = warp >> 2;

    const __nv_bfloat16* Rhi_b = g_Rhi + (size_t)b * N_ * D_;
    const __nv_bfloat16* Rlo_b = g_Rlo + (size_t)b * N_ * D_;
    const __nv_bfloat16* Vhi_b = g_Vhi + (size_t)b * N_ * D_;
    const __nv_bfloat16* Vlo_b = g_Vlo + (size_t)b * N_ * D_;

    // ---- load resident A tile: 2 parts x 128 rows x 32 u16B-units per row
#pragma unroll
    for (int it = 0; it < 32; ++it) {
        int u = tid + it * 256;            // 0..8191
        int part = u >> 12;
        int rem  = u & 4095;
        int row  = rem >> 5;
        int ku   = rem & 31;
        int gr   = min(row0 + row, ni - 1);
        const uint4* src = (const uint4*)((part ? Rlo_b : Rhi_b) + (size_t)gr * D_) + ku;
        uint32_t off = SM_A + (uint32_t)part * 65536u
                     + (uint32_t)((row >> 3) * 4 + (ku >> 3)) * 1024u
                     + (uint32_t)(row & 7) * 128u + (uint32_t)(ku & 7) * 16u;
        *(uint4*)(smem + sw128(off)) = *src;
    }

    float acc[2][8][4];
#pragma unroll
    for (int mf = 0; mf < 2; ++mf)
#pragma unroll
        for (int nf = 0; nf < 8; ++nf)
#pragma unroll
            for (int q = 0; q < 4; ++q) acc[mf][nf][q] = 0.0f;
    float rm[4] = {-INFINITY, -INFINITY, -INFINITY, -INFINITY};

    int Tj = (jend - jbeg + 127) >> 7;
    int NC = Tj * 4;

    // chunk copier: chunk c covers j-tile (c>>2), k range (c&3)*64, both parts
    auto cp_chunk = [&](int c, int bufsel) {
        int jt = c >> 2, kc = c & 3;
        int col0 = jbeg + jt * 128;
#pragma unroll
        for (int i = 0; i < 8; ++i) {
            int u = tid + i * 256;          // 0..2047
            int part = u >> 10;
            int rem  = u & 1023;
            int col  = rem >> 3;
            int ku   = rem & 7;
            int gc   = col0 + col;
            const void* src = (const void*)((part ? Vlo_b : Vhi_b)
                              + (size_t)gc * D_ + kc * 64 + ku * 8);
            uint32_t off = SM_B + (uint32_t)bufsel * 32768u + (uint32_t)part * 16384u
                         + (uint32_t)(col >> 3) * 1024u
                         + (uint32_t)(col & 7) * 128u + (uint32_t)ku * 16u;
            cp_async16(sb + sw128(off), src, (gc < jend) ? 16 : 0);
        }
        cp_commit();
    };

    cp_chunk(0, 0);
    __syncthreads();   // A tile visible to all

    for (int i = 0; i < NC; ++i) {
        int bufsel = i & 1;
        int kc = i & 3;
        if (i + 1 < NC) { cp_chunk(i + 1, (i + 1) & 1); cp_wait<1>(); }
        else            { cp_wait<0>(); }
        __syncthreads();

        // ---- compute chunk: per k16 step load all fragments once, 48 HMMA
#pragma unroll
        for (int kk = 0; kk < 4; ++kk) {
            uint32_t ahi[2][4], alo[2][4];
#pragma unroll
            for (int mf = 0; mf < 2; ++mf) {
                int row = warp_m * 32 + mf * 16 + (lane & 15);
                int ku  = (kc * 4 + kk) * 2 + (lane >> 4);
                uint32_t offbase = (uint32_t)((row >> 3) * 4 + (ku >> 3)) * 1024u
                                 + (uint32_t)(row & 7) * 128u
                                 + (uint32_t)(ku & 7) * 16u;
                ldmatrix_x4(ahi[mf], sb + sw128(SM_A + offbase));
                ldmatrix_x4(alo[mf], sb + sw128(SM_A + 65536u + offbase));
            }
            uint32_t bhi[4][4], blo[4][4];
#pragma unroll
            for (int nf2 = 0; nf2 < 4; ++nf2) {
                int col = warp_n * 64 + nf2 * 16 + (lane & 15);
                int ku  = kk * 2 + (lane >> 4);
                uint32_t offbase = (uint32_t)bufsel * 32768u
                                 + (uint32_t)(col >> 3) * 1024u
                                 + (uint32_t)(col & 7) * 128u
                                 + (uint32_t)ku * 16u;
                ldmatrix_x4(bhi[nf2], sb + sw128(SM_B + offbase));
                ldmatrix_x4(blo[nf2], sb + sw128(SM_B + 16384u + offbase));
            }
#pragma unroll
            for (int mf = 0; mf < 2; ++mf)
#pragma unroll
                for (int nf2 = 0; nf2 < 4; ++nf2) {
                    float* c0 = acc[mf][nf2 * 2];
                    float* c1 = acc[mf][nf2 * 2 + 1];
                    mma16816(c0, ahi[mf], bhi[nf2][0], bhi[nf2][2]);
                    mma16816(c1, ahi[mf], bhi[nf2][1], bhi[nf2][3]);
                    mma16816(c0, ahi[mf], blo[nf2][0], blo[nf2][2]);
                    mma16816(c1, ahi[mf], blo[nf2][1], blo[nf2][3]);
                    mma16816(c0, alo[mf], bhi[nf2][0], bhi[nf2][2]);
                    mma16816(c1, alo[mf], bhi[nf2][1], bhi[nf2][3]);
                }
        }

        if (kc == 3) {
            // end of j-tile: fold accumulators into running row-max, reset
#pragma unroll
            for (int mf = 0; mf < 2; ++mf) {
                float m0 = rm[mf * 2], m1 = rm[mf * 2 + 1];
#pragma unroll
                for (int nf = 0; nf < 8; ++nf) {
                    m0 = fmaxf(m0, fmaxf(acc[mf][nf][0], acc[mf][nf][1]));
                    m1 = fmaxf(m1, fmaxf(acc[mf][nf][2], acc[mf][nf][3]));
#pragma unroll
                    for (int q = 0; q < 4; ++q) acc[mf][nf][q] = 0.0f;
                }
                rm[mf * 2] = m0; rm[mf * 2 + 1] = m1;
            }
        }
        __syncthreads();
    }

    // ---- reduce row maxima: lanes sharing a row are lane%4 groups
#pragma unroll
    for (int j = 0; j < 4; ++j) {
        rm[j] = fmaxf(rm[j], __shfl_xor_sync(0xffffffffu, rm[j], 1));
        rm[j] = fmaxf(rm[j], __shfl_xor_sync(0xffffffffu, rm[j], 2));
    }
    float* smax = (float*)(smem + SM_MAX);
    if ((lane & 3) == 0) {
        int rbase = warp_m * 32 + (lane >> 2);
#pragma unroll
        for (int mf = 0; mf < 2; ++mf) {
            smax[warp_n * 128 + rbase + mf * 16]     = rm[mf * 2];
            smax[warp_n * 128 + rbase + mf * 16 + 8] = rm[mf * 2 + 1];
        }
    }
    __syncthreads();
    if (tid < 128) {
        int row = row0 + tid;
        if (row < ni) {
            float m = fmaxf(smax[tid], smax[128 + tid]);
            atomicMax(&g_rmax[b * N_ + row], enc_max(m));
        }
    }
}

// ---------------- confidence / contribution pass ----------------
__global__ void confident_kernel() {
    int i = blockIdx.x * blockDim.x + threadIdx.x;
    if (i >= B_ * N_) return;
    int b = i / N_;
    int row = i - b * N_;
    if (g_nval[b] <= 0) return;
    if (row >= g_ninv[b]) return;
    float m = dec_max(g_rmax[i]);
    if (m > CONF_THRESH) {
        atomicAdd(&g_contrib[b], (double)(1.0f - m));
        atomicAdd(&g_nconf[b], 1);
    }
}

// ---------------- finalize ----------------
__global__ void finalize_kernel(float* out) {
    if (threadIdx.x == 0 && blockIdx.x == 0) {
        double tl = 0.0, tp = 0.0;
        for (int b = 0; b < B_; ++b) {
            int ni = g_ninv[b], nvv = g_nval[b], nc = g_nconf[b];
            bool active = (nc > 0) && (nvv > 0) && (ni > 0);
            if (active) {
                double pseudo = g_contrib[b] / (double)(nc > 1 ? nc : 1);
                tl += pseudo * (double)ni;
                tp += (double)ni;
            }
        }
        out[0] = (tp > 0.0) ? (float)(0.01 * tl / tp) : 0.0f;
    }
}

// ---------------- launch ----------------
extern "C" void kernel_launch(void* const* d_in, const int* in_sizes, int n_in,
                              void* d_out, int out_size) {
    int fi = 0, mi = 1;
    if (n_in >= 2 && in_sizes[0] < in_sizes[1]) { fi = 1; mi = 0; }
    const float* feat = (const float*)d_in[fi];
    const void*  mask = d_in[mi];

    cudaFuncSetAttribute(maxsim_hmma, cudaFuncAttributeMaxDynamicSharedMemorySize,
                         SMEM_BYTES);

    init_kernel<<<(B_ * N_ + 255) / 256, 256>>>();
    detect_kernel<<<1, 1024>>>((const unsigned char*)mask);
    norm_compact_kernel<<<(B_ * N_ * 32 + 255) / 256, 256>>>(feat, mask);
    dim3 g(N_ / 128, B_, JSPLIT);
    maxsim_hmma<<<g, 256, SMEM_BYTES>>>();
    confident_kernel<<<(B_ * N_ + 255) / 256, 256>>>();
    finalize_kernel<<<1, 32>>>((float*)d_out);
}